// round 3
// baseline (speedup 1.0000x reference)
#include <cuda_runtime.h>
#include <math.h>

#define DD 280
#define HH 7
#define HDD 40
#define LL 7
#define FFD 1120
#define VV 256
#define TT 512
#define BB 32
#define MM (BB*TT)   // 16384

// ---------------- scratch (device globals; no allocation allowed) ----------------
__device__ float g_x[MM*DD];
__device__ float g_h[MM*DD];
__device__ float g_q[MM*DD];
__device__ float g_k[MM*DD];
__device__ float g_v[MM*DD];
__device__ float g_o[MM*DD];
__device__ float g_gp[(size_t)MM*FFD];
__device__ float g_att[(size_t)BB*HH*TT*TT];

// ---------------- embed ----------------
__global__ void k_embed(const int* __restrict__ idx, const float* __restrict__ emb,
                        float* __restrict__ x) {
    int i = blockIdx.x * 256 + threadIdx.x;
    if (i >= MM * DD) return;
    int m = i / DD;
    int d = i - m * DD;
    x[i] = emb[idx[m] * DD + d];
}

// ---------------- rmsnorm (block per row, 128 threads) ----------------
__global__ void k_rmsnorm(const float* __restrict__ x, const float* __restrict__ w,
                          float* __restrict__ out) {
    int m = blockIdx.x;
    const float* xr = x + (size_t)m * DD;
    float ss = 0.f;
    for (int d = threadIdx.x; d < DD; d += 128) { float t = xr[d]; ss += t * t; }
    #pragma unroll
    for (int o = 16; o; o >>= 1) ss += __shfl_xor_sync(0xffffffffu, ss, o);
    __shared__ float red[4];
    __shared__ float s_scale;
    int wid = threadIdx.x >> 5;
    if ((threadIdx.x & 31) == 0) red[wid] = ss;
    __syncthreads();
    if (threadIdx.x == 0) {
        float tot = red[0] + red[1] + red[2] + red[3];
        s_scale = rsqrtf(tot / (float)DD + 1e-6f);
    }
    __syncthreads();
    float sc = s_scale;
    for (int d = threadIdx.x; d < DD; d += 128)
        out[(size_t)m * DD + d] = xr[d] * sc * w[d];
}

// ---------------- generic GEMM: C[M,N] = A[M,K] * W[N,K]^T (optionally += residual) ----
// 64x64 tile, BK=16, 256 threads, 4x4 per thread, float4 smem reads.
template<bool ADD>
__global__ void k_gemm(const float* __restrict__ A, const float* __restrict__ W,
                       float* __restrict__ C, int N, int K) {
    __shared__ float As[16][64];
    __shared__ float Ws[16][64];
    int m0 = blockIdx.y * 64, n0 = blockIdx.x * 64;
    int tid = threadIdx.x;
    int tx = tid & 15, ty = tid >> 4;
    int ml  = tid >> 2;          // 0..63
    int kk0 = (tid & 3) * 4;     // 0,4,8,12
    const float* ap = A + (size_t)(m0 + ml) * K;
    const float* wp = W + (size_t)(n0 + ml) * K;
    bool wok = (n0 + ml) < N;
    float acc[4][4] = {};
    for (int k0 = 0; k0 < K; k0 += 16) {
        #pragma unroll
        for (int i = 0; i < 4; i++) {
            int k = k0 + kk0 + i;
            As[kk0 + i][ml] = (k < K) ? ap[k] : 0.f;
            Ws[kk0 + i][ml] = (wok && k < K) ? wp[k] : 0.f;
        }
        __syncthreads();
        #pragma unroll
        for (int kk = 0; kk < 16; kk++) {
            float4 av = *reinterpret_cast<const float4*>(&As[kk][ty * 4]);
            float4 wv = *reinterpret_cast<const float4*>(&Ws[kk][tx * 4]);
            float aa[4] = {av.x, av.y, av.z, av.w};
            float ww[4] = {wv.x, wv.y, wv.z, wv.w};
            #pragma unroll
            for (int i = 0; i < 4; i++)
                #pragma unroll
                for (int j = 0; j < 4; j++)
                    acc[i][j] += aa[i] * ww[j];
        }
        __syncthreads();
    }
    #pragma unroll
    for (int i = 0; i < 4; i++) {
        int m = m0 + ty * 4 + i;
        #pragma unroll
        for (int j = 0; j < 4; j++) {
            int n = n0 + tx * 4 + j;
            if (n < N) {
                size_t o = (size_t)m * N + n;
                C[o] = ADD ? (C[o] + acc[i][j]) : acc[i][j];
            }
        }
    }
}

// ---------------- fused MLP gate: Gp = silu(A*W1^T) * (A*W3^T), N=FFD, K=DD ----------
__global__ void k_mlp(const float* __restrict__ A, const float* __restrict__ W1,
                      const float* __restrict__ W3, float* __restrict__ Gp) {
    __shared__ float As[16][64];
    __shared__ float W1s[16][64];
    __shared__ float W3s[16][64];
    const int K = DD, N = FFD;
    int m0 = blockIdx.y * 64, n0 = blockIdx.x * 64;
    int tid = threadIdx.x;
    int tx = tid & 15, ty = tid >> 4;
    int ml  = tid >> 2;
    int kk0 = (tid & 3) * 4;
    const float* ap  = A  + (size_t)(m0 + ml) * K;
    const float* w1p = W1 + (size_t)(n0 + ml) * K;
    const float* w3p = W3 + (size_t)(n0 + ml) * K;
    bool wok = (n0 + ml) < N;
    float acc1[4][4] = {};
    float acc3[4][4] = {};
    for (int k0 = 0; k0 < K; k0 += 16) {
        #pragma unroll
        for (int i = 0; i < 4; i++) {
            int k = k0 + kk0 + i;
            As [kk0 + i][ml] = (k < K) ? ap[k] : 0.f;
            W1s[kk0 + i][ml] = (wok && k < K) ? w1p[k] : 0.f;
            W3s[kk0 + i][ml] = (wok && k < K) ? w3p[k] : 0.f;
        }
        __syncthreads();
        #pragma unroll
        for (int kk = 0; kk < 16; kk++) {
            float4 av = *reinterpret_cast<const float4*>(&As [kk][ty * 4]);
            float4 v1 = *reinterpret_cast<const float4*>(&W1s[kk][tx * 4]);
            float4 v3 = *reinterpret_cast<const float4*>(&W3s[kk][tx * 4]);
            float aa[4] = {av.x, av.y, av.z, av.w};
            float b1[4] = {v1.x, v1.y, v1.z, v1.w};
            float b3[4] = {v3.x, v3.y, v3.z, v3.w};
            #pragma unroll
            for (int i = 0; i < 4; i++)
                #pragma unroll
                for (int j = 0; j < 4; j++) {
                    acc1[i][j] += aa[i] * b1[j];
                    acc3[i][j] += aa[i] * b3[j];
                }
        }
        __syncthreads();
    }
    #pragma unroll
    for (int i = 0; i < 4; i++) {
        int m = m0 + ty * 4 + i;
        #pragma unroll
        for (int j = 0; j < 4; j++) {
            int n = n0 + tx * 4 + j;
            if (n < N) {
                float g = acc1[i][j];
                float u = acc3[i][j];
                float s = g / (1.f + __expf(-g));   // silu
                Gp[(size_t)m * N + n] = s * u;
            }
        }
    }
}

// ---------------- rotary (q and k in-place) ----------------
__global__ void k_rotary(float* __restrict__ q, float* __restrict__ k) {
    int i = blockIdx.x * 256 + threadIdx.x;
    if (i >= MM * HH * (HDD / 2)) return;
    int p  = i % 20;
    int mh = i / 20;
    int h  = mh % HH;
    int m  = mh / HH;
    int t  = m & (TT - 1);
    float f = expf(-0.4605170186f * (float)p);   // 10000^{-p/20}
    float sv, cv;
    sincosf((float)t * f, &sv, &cv);
    size_t base = (size_t)m * DD + h * HDD + p;
    float a = q[base], b2 = q[base + 20];
    q[base]      = a  * cv - b2 * sv;
    q[base + 20] = b2 * cv + a  * sv;
    a = k[base]; b2 = k[base + 20];
    k[base]      = a  * cv - b2 * sv;
    k[base + 20] = b2 * cv + a  * sv;
}

// ---------------- attention scores: att[bh,t,s] = scale * q.k (masked) ---------------
// grid (8 s-tiles, 8 t-tiles, B*H); fully-masked tiles skipped.
__global__ void k_score(const float* __restrict__ q, const float* __restrict__ k,
                        float* __restrict__ att) {
    if (blockIdx.x > blockIdx.y) return;          // tile fully above diagonal
    int st0 = blockIdx.x * 64, tt0 = blockIdx.y * 64;
    int bh = blockIdx.z;
    int b = bh / HH, h = bh - b * HH;
    const float* qb = q + (size_t)b * TT * DD + h * HDD;
    const float* kb = k + (size_t)b * TT * DD + h * HDD;
    __shared__ float Qs[64][HDD];
    __shared__ float Ks[64][HDD];
    int tid = threadIdx.x;
    for (int i = tid; i < 64 * HDD; i += 256) {
        int r = i / HDD, c = i - r * HDD;
        Qs[r][c] = qb[(size_t)(tt0 + r) * DD + c];
        Ks[r][c] = kb[(size_t)(st0 + r) * DD + c];
    }
    __syncthreads();
    int tx = tid & 15, ty = tid >> 4;
    float acc[4][4] = {};
    #pragma unroll
    for (int kc = 0; kc < HDD; kc += 4) {
        float4 a[4], bb[4];
        #pragma unroll
        for (int i = 0; i < 4; i++) a[i]  = *reinterpret_cast<const float4*>(&Qs[ty * 4 + i][kc]);
        #pragma unroll
        for (int j = 0; j < 4; j++) bb[j] = *reinterpret_cast<const float4*>(&Ks[tx * 4 + j][kc]);
        #pragma unroll
        for (int i = 0; i < 4; i++)
            #pragma unroll
            for (int j = 0; j < 4; j++)
                acc[i][j] += a[i].x * bb[j].x + a[i].y * bb[j].y +
                             a[i].z * bb[j].z + a[i].w * bb[j].w;
    }
    const float scale = 0.1581138830f;  // 40^-0.5
    float* arow = att + ((size_t)bh * TT + tt0) * TT + st0;
    #pragma unroll
    for (int i = 0; i < 4; i++) {
        int t = tt0 + ty * 4 + i;
        #pragma unroll
        for (int j = 0; j < 4; j++) {
            int s = st0 + tx * 4 + j;
            arow[(size_t)(ty * 4 + i) * TT + tx * 4 + j] =
                (s <= t) ? acc[i][j] * scale : -1e30f;
        }
    }
}

// ---------------- causal softmax in-place (block per row) ----------------
__global__ void k_softmax(float* __restrict__ att) {
    int row = blockIdx.x;                  // bh*T + t
    int t = row & (TT - 1);
    float* p = att + (size_t)row * TT;
    int len = t + 1;
    int tid = threadIdx.x;
    __shared__ float s_red[8];
    __shared__ float s_b;

    float mx = -3.4e38f;
    for (int s = tid; s < len; s += 256) mx = fmaxf(mx, p[s]);
    #pragma unroll
    for (int o = 16; o; o >>= 1) mx = fmaxf(mx, __shfl_xor_sync(0xffffffffu, mx, o));
    if ((tid & 31) == 0) s_red[tid >> 5] = mx;
    __syncthreads();
    if (tid == 0) {
        float m2 = s_red[0];
        #pragma unroll
        for (int i = 1; i < 8; i++) m2 = fmaxf(m2, s_red[i]);
        s_b = m2;
    }
    __syncthreads();
    mx = s_b;

    float sum = 0.f;
    for (int s = tid; s < len; s += 256) {
        float e = __expf(p[s] - mx);
        p[s] = e;
        sum += e;
    }
    #pragma unroll
    for (int o = 16; o; o >>= 1) sum += __shfl_xor_sync(0xffffffffu, sum, o);
    if ((tid & 31) == 0) s_red[tid >> 5] = sum;
    __syncthreads();
    if (tid == 0) {
        float tot = 0.f;
        #pragma unroll
        for (int i = 0; i < 8; i++) tot += s_red[i];
        s_b = 1.f / tot;
    }
    __syncthreads();
    float inv = s_b;
    for (int s = tid; s < TT; s += 256) {
        if (s < len) p[s] *= inv;
        else         p[s] = 0.f;
    }
}

// ---------------- PV: o[t, h*40+d] = sum_s p[t,s] v[s, h*40+d] ----------------
// grid (T/64, B*H), 256 threads; K-loop bounded by causality (p==0 beyond).
__global__ void k_pv(const float* __restrict__ att, const float* __restrict__ v,
                     float* __restrict__ o) {
    int tt0 = blockIdx.x * 64;
    int bh = blockIdx.y;
    int b = bh / HH, h = bh - b * HH;
    const float* p  = att + ((size_t)bh * TT + tt0) * TT;
    const float* vb = v + (size_t)b * TT * DD + h * HDD;
    float* ob       = o + ((size_t)b * TT + tt0) * DD + h * HDD;
    int smax = tt0 + 64;                 // p is zero beyond the query tile's diagonal
    __shared__ float Ps[64][33];         // +1 pad kills bank conflicts on row reads
    __shared__ float Vs[32][HDD];
    int tid = threadIdx.x;
    int tx = tid & 7, ty = tid >> 3;     // 8 col-groups x 5, 32 row-groups x 2
    float acc[2][5] = {};
    for (int s0 = 0; s0 < smax; s0 += 32) {
        for (int i = tid; i < 64 * 32; i += 256) {
            int r = i >> 5, c = i & 31;
            Ps[r][c] = p[(size_t)r * TT + s0 + c];
        }
        for (int i = tid; i < 32 * HDD; i += 256) {
            int r = i / HDD, c = i - r * HDD;
            Vs[r][c] = vb[(size_t)(s0 + r) * DD + c];
        }
        __syncthreads();
        #pragma unroll
        for (int kk = 0; kk < 32; kk++) {
            float p0 = Ps[ty * 2 + 0][kk];
            float p1 = Ps[ty * 2 + 1][kk];
            #pragma unroll
            for (int j = 0; j < 5; j++) {
                float vv = Vs[kk][tx * 5 + j];
                acc[0][j] += p0 * vv;
                acc[1][j] += p1 * vv;
            }
        }
        __syncthreads();
    }
    #pragma unroll
    for (int i = 0; i < 2; i++)
        #pragma unroll
        for (int j = 0; j < 5; j++)
            ob[(size_t)(ty * 2 + i) * DD + tx * 5 + j] = acc[i][j];
}

// ---------------- launcher ----------------
extern "C" void kernel_launch(void* const* d_in, const int* in_sizes, int n_in,
                              void* d_out, int out_size) {
    const int*   idx = (const int*)  d_in[0];
    const float* emb = (const float*)d_in[1];
    const float* wq  = (const float*)d_in[2];
    const float* wk  = (const float*)d_in[3];
    const float* wv  = (const float*)d_in[4];
    const float* wo  = (const float*)d_in[5];
    const float* w1  = (const float*)d_in[6];
    const float* w2  = (const float*)d_in[7];
    const float* w3  = (const float*)d_in[8];
    const float* n1  = (const float*)d_in[9];
    const float* n2  = (const float*)d_in[10];
    const float* nw  = (const float*)d_in[11];
    float* out = (float*)d_out;

    float *x, *h, *q, *k, *v, *o, *gp, *att;
    cudaGetSymbolAddress((void**)&x,  g_x);
    cudaGetSymbolAddress((void**)&h,  g_h);
    cudaGetSymbolAddress((void**)&q,  g_q);
    cudaGetSymbolAddress((void**)&k,  g_k);
    cudaGetSymbolAddress((void**)&v,  g_v);
    cudaGetSymbolAddress((void**)&o,  g_o);
    cudaGetSymbolAddress((void**)&gp, g_gp);
    cudaGetSymbolAddress((void**)&att, g_att);

    k_embed<<<(MM * DD + 255) / 256, 256>>>(idx, emb, x);

    dim3 gD(5,  MM / 64);   // N = 280
    dim3 gF(18, MM / 64);   // N = 1120
    dim3 gV(4,  MM / 64);   // N = 256

    for (int l = 0; l < LL; l++) {
        size_t wOff = (size_t)l * DD * DD;
        k_rmsnorm<<<MM, 128>>>(x, n1 + l * DD, h);
        k_gemm<false><<<gD, 256>>>(h, wq + wOff, q, DD, DD);
        k_gemm<false><<<gD, 256>>>(h, wk + wOff, k, DD, DD);
        k_gemm<false><<<gD, 256>>>(h, wv + wOff, v, DD, DD);
        k_rotary<<<(MM * HH * 20 + 255) / 256, 256>>>(q, k);
        k_score<<<dim3(8, 8, BB * HH), 256>>>(q, k, att);
        k_softmax<<<BB * HH * TT, 256>>>(att);
        k_pv<<<dim3(TT / 64, BB * HH), 256>>>(att, v, o);
        k_gemm<true><<<gD, 256>>>(o, wo + wOff, x, DD, DD);
        k_rmsnorm<<<MM, 128>>>(x, n2 + l * DD, h);
        k_mlp<<<gF, 256>>>(h, w1 + (size_t)l * FFD * DD, w3 + (size_t)l * FFD * DD, gp);
        k_gemm<true><<<gD, 256>>>(gp, w2 + (size_t)l * DD * FFD, x, DD, FFD);
    }

    k_rmsnorm<<<MM, 128>>>(x, nw, h);
    k_gemm<false><<<gV, 256>>>(h, emb, out, VV, DD);
}

// round 5
// speedup vs baseline: 1.8184x; 1.8184x over previous
#include <cuda_runtime.h>
#include <math.h>

#define DD 280
#define HH 7
#define HDD 40
#define LL 7
#define FFD 1120
#define VV 256
#define TT 512
#define BB 32
#define MM (BB*TT)   // 16384

// ---------------- scratch (device globals; no allocation allowed) ----------------
__device__ float g_x[MM*DD];
__device__ float g_h[MM*DD];
__device__ float g_q[MM*DD];
__device__ float g_k[MM*DD];
__device__ float g_v[MM*DD];
__device__ float g_o[MM*DD];
__device__ float g_gp[(size_t)MM*FFD];
__device__ float g_att[(size_t)BB*HH*TT*TT];

// ---------------- helpers ----------------
__device__ __forceinline__ float to_tf32(float x) {
    unsigned u;
    asm("cvt.rna.tf32.f32 %0, %1;" : "=r"(u) : "f"(x));
    return __uint_as_float(u);
}

__device__ __forceinline__ void mma_tf32(float* d, const float* a, const float* b) {
    asm volatile(
        "mma.sync.aligned.m16n8k8.row.col.f32.tf32.tf32.f32 "
        "{%0,%1,%2,%3}, {%4,%5,%6,%7}, {%8,%9}, {%0,%1,%2,%3};\n"
        : "+f"(d[0]), "+f"(d[1]), "+f"(d[2]), "+f"(d[3])
        : "r"(__float_as_uint(a[0])), "r"(__float_as_uint(a[1])),
          "r"(__float_as_uint(a[2])), "r"(__float_as_uint(a[3])),
          "r"(__float_as_uint(b[0])), "r"(__float_as_uint(b[1])));
}

// ---------------- embed ----------------
__global__ void k_embed(const int* __restrict__ idx, const float* __restrict__ emb,
                        float* __restrict__ x) {
    int i = blockIdx.x * 256 + threadIdx.x;
    if (i >= MM * DD) return;
    int m = i / DD;
    int d = i - m * DD;
    x[i] = emb[idx[m] * DD + d];
}

// ---------------- rmsnorm (block per row, 128 threads) ----------------
__global__ void k_rmsnorm(const float* __restrict__ x, const float* __restrict__ w,
                          float* __restrict__ out) {
    int m = blockIdx.x;
    const float* xr = x + (size_t)m * DD;
    float ss = 0.f;
    for (int d = threadIdx.x; d < DD; d += 128) { float t = xr[d]; ss += t * t; }
    #pragma unroll
    for (int o = 16; o; o >>= 1) ss += __shfl_xor_sync(0xffffffffu, ss, o);
    __shared__ float red[4];
    __shared__ float s_scale;
    int wid = threadIdx.x >> 5;
    if ((threadIdx.x & 31) == 0) red[wid] = ss;
    __syncthreads();
    if (threadIdx.x == 0) {
        float tot = red[0] + red[1] + red[2] + red[3];
        s_scale = rsqrtf(tot / (float)DD + 1e-6f);
    }
    __syncthreads();
    float sc = s_scale;
    for (int d = threadIdx.x; d < DD; d += 128)
        out[(size_t)m * DD + d] = xr[d] * sc * w[d];
}

// ============ tensor-core GEMM: C[M,N] = A[M,K] * W[N,K]^T (opt. +=) ============
// Block tile 128x64, BK=16, 256 threads = 8 warps in 4(m) x 2(n) grid,
// warp tile 32x32 (2 m16-tiles x 4 n8-tiles), mma.m16n8k8.tf32.
// SMEM stride 20 floats -> conflict-free fragment LDS for the (g,q) pattern.
template<bool ADD>
__global__ void __launch_bounds__(256) k_gemm_tc(
        const float* __restrict__ A, const float* __restrict__ W,
        float* __restrict__ C, int N, int K) {
    __shared__ __align__(16) float As[128][20];
    __shared__ __align__(16) float Ws[64][20];
    int m0 = blockIdx.y * 128, n0 = blockIdx.x * 64;
    int tid = threadIdx.x;
    int lane = tid & 31, warp = tid >> 5;
    int wm = (warp & 3) * 32, wn = (warp >> 2) * 32;
    int g = lane >> 2, q = lane & 3;

    int lrow = tid >> 2;            // 0..63
    int lcol = (tid & 3) * 4;       // 0,4,8,12
    const float* a0p = A + (size_t)(m0 + lrow) * K;
    const float* a1p = A + (size_t)(m0 + lrow + 64) * K;
    const float* wp  = W + (size_t)(n0 + lrow) * K;
    bool wok = (n0 + lrow) < N;

    float acc[2][4][4] = {};

    for (int k0 = 0; k0 < K; k0 += 16) {
        int gk = k0 + lcol;
        bool kok = (gk + 3) < K;    // K%4==0 so float4 is all-valid or all-invalid
        float4 va = kok ? *(const float4*)(a0p + gk) : make_float4(0,0,0,0);
        float4 vb = kok ? *(const float4*)(a1p + gk) : make_float4(0,0,0,0);
        float4 vw = (kok && wok) ? *(const float4*)(wp + gk) : make_float4(0,0,0,0);
        va.x = to_tf32(va.x); va.y = to_tf32(va.y); va.z = to_tf32(va.z); va.w = to_tf32(va.w);
        vb.x = to_tf32(vb.x); vb.y = to_tf32(vb.y); vb.z = to_tf32(vb.z); vb.w = to_tf32(vb.w);
        vw.x = to_tf32(vw.x); vw.y = to_tf32(vw.y); vw.z = to_tf32(vw.z); vw.w = to_tf32(vw.w);
        *(float4*)(&As[lrow][lcol])      = va;
        *(float4*)(&As[lrow + 64][lcol]) = vb;
        *(float4*)(&Ws[lrow][lcol])      = vw;
        __syncthreads();

        #pragma unroll
        for (int ks = 0; ks < 2; ks++) {
            int kb = ks * 8;
            float a[2][4];
            #pragma unroll
            for (int mt = 0; mt < 2; mt++) {
                int r = wm + mt * 16;
                a[mt][0] = As[r + g    ][kb + q];
                a[mt][1] = As[r + g + 8][kb + q];
                a[mt][2] = As[r + g    ][kb + q + 4];
                a[mt][3] = As[r + g + 8][kb + q + 4];
            }
            float b[4][2];
            #pragma unroll
            for (int nt = 0; nt < 4; nt++) {
                int c = wn + nt * 8;
                b[nt][0] = Ws[c + g][kb + q];
                b[nt][1] = Ws[c + g][kb + q + 4];
            }
            #pragma unroll
            for (int mt = 0; mt < 2; mt++)
                #pragma unroll
                for (int nt = 0; nt < 4; nt++)
                    mma_tf32(acc[mt][nt], a[mt], b[nt]);
        }
        __syncthreads();
    }

    #pragma unroll
    for (int mt = 0; mt < 2; mt++) {
        int r0 = m0 + wm + mt * 16 + g;
        #pragma unroll
        for (int nt = 0; nt < 4; nt++) {
            int c0 = n0 + wn + nt * 8 + 2 * q;
            if (c0 < N) {          // N even, c0 even -> pair valid together
                float* d = acc[mt][nt];
                size_t o1 = (size_t)r0 * N + c0;
                size_t o2 = (size_t)(r0 + 8) * N + c0;
                if (ADD) {
                    C[o1] += d[0]; C[o1 + 1] += d[1];
                    C[o2] += d[2]; C[o2 + 1] += d[3];
                } else {
                    C[o1] = d[0]; C[o1 + 1] = d[1];
                    C[o2] = d[2]; C[o2 + 1] = d[3];
                }
            }
        }
    }
}

// ============ fused MLP: Gp = silu(A*W1^T) * (A*W3^T), tensor cores ============
__global__ void __launch_bounds__(256) k_mlp_tc(
        const float* __restrict__ A, const float* __restrict__ W1,
        const float* __restrict__ W3, float* __restrict__ Gp) {
    const int K = DD, N = FFD;
    __shared__ __align__(16) float As[128][20];
    __shared__ __align__(16) float W1s[64][20];
    __shared__ __align__(16) float W3s[64][20];
    int m0 = blockIdx.y * 128, n0 = blockIdx.x * 64;
    int tid = threadIdx.x;
    int lane = tid & 31, warp = tid >> 5;
    int wm = (warp & 3) * 32, wn = (warp >> 2) * 32;
    int g = lane >> 2, q = lane & 3;

    int lrow = tid >> 2;
    int lcol = (tid & 3) * 4;
    const float* a0p = A  + (size_t)(m0 + lrow) * K;
    const float* a1p = A  + (size_t)(m0 + lrow + 64) * K;
    const float* w1p = W1 + (size_t)(n0 + lrow) * K;
    const float* w3p = W3 + (size_t)(n0 + lrow) * K;
    bool wok = (n0 + lrow) < N;

    float acc1[2][4][4] = {};
    float acc3[2][4][4] = {};

    for (int k0 = 0; k0 < K; k0 += 16) {
        int gk = k0 + lcol;
        bool kok = (gk + 3) < K;
        float4 va = kok ? *(const float4*)(a0p + gk) : make_float4(0,0,0,0);
        float4 vb = kok ? *(const float4*)(a1p + gk) : make_float4(0,0,0,0);
        float4 v1 = (kok && wok) ? *(const float4*)(w1p + gk) : make_float4(0,0,0,0);
        float4 v3 = (kok && wok) ? *(const float4*)(w3p + gk) : make_float4(0,0,0,0);
        va.x = to_tf32(va.x); va.y = to_tf32(va.y); va.z = to_tf32(va.z); va.w = to_tf32(va.w);
        vb.x = to_tf32(vb.x); vb.y = to_tf32(vb.y); vb.z = to_tf32(vb.z); vb.w = to_tf32(vb.w);
        v1.x = to_tf32(v1.x); v1.y = to_tf32(v1.y); v1.z = to_tf32(v1.z); v1.w = to_tf32(v1.w);
        v3.x = to_tf32(v3.x); v3.y = to_tf32(v3.y); v3.z = to_tf32(v3.z); v3.w = to_tf32(v3.w);
        *(float4*)(&As[lrow][lcol])      = va;
        *(float4*)(&As[lrow + 64][lcol]) = vb;
        *(float4*)(&W1s[lrow][lcol])     = v1;
        *(float4*)(&W3s[lrow][lcol])     = v3;
        __syncthreads();

        #pragma unroll
        for (int ks = 0; ks < 2; ks++) {
            int kb = ks * 8;
            float a[2][4];
            #pragma unroll
            for (int mt = 0; mt < 2; mt++) {
                int r = wm + mt * 16;
                a[mt][0] = As[r + g    ][kb + q];
                a[mt][1] = As[r + g + 8][kb + q];
                a[mt][2] = As[r + g    ][kb + q + 4];
                a[mt][3] = As[r + g + 8][kb + q + 4];
            }
            #pragma unroll
            for (int nt = 0; nt < 4; nt++) {
                int c = wn + nt * 8;
                float b1[2], b3[2];
                b1[0] = W1s[c + g][kb + q];
                b1[1] = W1s[c + g][kb + q + 4];
                b3[0] = W3s[c + g][kb + q];
                b3[1] = W3s[c + g][kb + q + 4];
                #pragma unroll
                for (int mt = 0; mt < 2; mt++) {
                    mma_tf32(acc1[mt][nt], a[mt], b1);
                    mma_tf32(acc3[mt][nt], a[mt], b3);
                }
            }
        }
        __syncthreads();
    }

    #pragma unroll
    for (int mt = 0; mt < 2; mt++) {
        int r0 = m0 + wm + mt * 16 + g;
        #pragma unroll
        for (int nt = 0; nt < 4; nt++) {
            int c0 = n0 + wn + nt * 8 + 2 * q;
            if (c0 < N) {
                #pragma unroll
                for (int e = 0; e < 4; e++) {
                    float gg = acc1[mt][nt][e];
                    float uu = acc3[mt][nt][e];
                    float sv = gg / (1.f + __expf(-gg));
                    int row = (e < 2) ? r0 : r0 + 8;
                    int col = c0 + (e & 1);
                    Gp[(size_t)row * N + col] = sv * uu;
                }
            }
        }
    }
}

// ---------------- rotary (q and k in-place) ----------------
__global__ void k_rotary(float* __restrict__ q, float* __restrict__ k) {
    int i = blockIdx.x * 256 + threadIdx.x;
    if (i >= MM * HH * (HDD / 2)) return;
    int p  = i % 20;
    int mh = i / 20;
    int h  = mh % HH;
    int m  = mh / HH;
    int t  = m & (TT - 1);
    float f = expf(-0.4605170186f * (float)p);   // 10000^{-p/20}
    float sv, cv;
    sincosf((float)t * f, &sv, &cv);
    size_t base = (size_t)m * DD + h * HDD + p;
    float a = q[base], b2 = q[base + 20];
    q[base]      = a  * cv - b2 * sv;
    q[base + 20] = b2 * cv + a  * sv;
    a = k[base]; b2 = k[base + 20];
    k[base]      = a  * cv - b2 * sv;
    k[base + 20] = b2 * cv + a  * sv;
}

// ---------------- attention scores: att[bh,t,s] = scale * q.k (masked) ---------------
__global__ void k_score(const float* __restrict__ q, const float* __restrict__ k,
                        float* __restrict__ att) {
    if (blockIdx.x > blockIdx.y) return;          // tile fully above diagonal
    int st0 = blockIdx.x * 64, tt0 = blockIdx.y * 64;
    int bh = blockIdx.z;
    int b = bh / HH, h = bh - b * HH;
    const float* qb = q + (size_t)b * TT * DD + h * HDD;
    const float* kb = k + (size_t)b * TT * DD + h * HDD;
    __shared__ float Qs[64][HDD];
    __shared__ float Ks[64][HDD];
    int tid = threadIdx.x;
    for (int i = tid; i < 64 * HDD; i += 256) {
        int r = i / HDD, c = i - r * HDD;
        Qs[r][c] = qb[(size_t)(tt0 + r) * DD + c];
        Ks[r][c] = kb[(size_t)(st0 + r) * DD + c];
    }
    __syncthreads();
    int tx = tid & 15, ty = tid >> 4;
    float acc[4][4] = {};
    #pragma unroll
    for (int kc = 0; kc < HDD; kc += 4) {
        float4 a[4], bb[4];
        #pragma unroll
        for (int i = 0; i < 4; i++) a[i]  = *reinterpret_cast<const float4*>(&Qs[ty * 4 + i][kc]);
        #pragma unroll
        for (int j = 0; j < 4; j++) bb[j] = *reinterpret_cast<const float4*>(&Ks[tx * 4 + j][kc]);
        #pragma unroll
        for (int i = 0; i < 4; i++)
            #pragma unroll
            for (int j = 0; j < 4; j++)
                acc[i][j] += a[i].x * bb[j].x + a[i].y * bb[j].y +
                             a[i].z * bb[j].z + a[i].w * bb[j].w;
    }
    const float scale = 0.1581138830f;  // 40^-0.5
    float* arow = att + ((size_t)bh * TT + tt0) * TT + st0;
    #pragma unroll
    for (int i = 0; i < 4; i++) {
        int t = tt0 + ty * 4 + i;
        #pragma unroll
        for (int j = 0; j < 4; j++) {
            int s = st0 + tx * 4 + j;
            arow[(size_t)(ty * 4 + i) * TT + tx * 4 + j] =
                (s <= t) ? acc[i][j] * scale : -1e30f;
        }
    }
}

// ---------------- causal softmax in-place (block per row) ----------------
__global__ void k_softmax(float* __restrict__ att) {
    int row = blockIdx.x;                  // bh*T + t
    int t = row & (TT - 1);
    float* p = att + (size_t)row * TT;
    int len = t + 1;
    int tid = threadIdx.x;
    __shared__ float s_red[8];
    __shared__ float s_b;

    float mx = -3.4e38f;
    for (int s = tid; s < len; s += 256) mx = fmaxf(mx, p[s]);
    #pragma unroll
    for (int o = 16; o; o >>= 1) mx = fmaxf(mx, __shfl_xor_sync(0xffffffffu, mx, o));
    if ((tid & 31) == 0) s_red[tid >> 5] = mx;
    __syncthreads();
    if (tid == 0) {
        float m2 = s_red[0];
        #pragma unroll
        for (int i = 1; i < 8; i++) m2 = fmaxf(m2, s_red[i]);
        s_b = m2;
    }
    __syncthreads();
    mx = s_b;

    float sum = 0.f;
    for (int s = tid; s < len; s += 256) {
        float e = __expf(p[s] - mx);
        p[s] = e;
        sum += e;
    }
    #pragma unroll
    for (int o = 16; o; o >>= 1) sum += __shfl_xor_sync(0xffffffffu, sum, o);
    if ((tid & 31) == 0) s_red[tid >> 5] = sum;
    __syncthreads();
    if (tid == 0) {
        float tot = 0.f;
        #pragma unroll
        for (int i = 0; i < 8; i++) tot += s_red[i];
        s_b = 1.f / tot;
    }
    __syncthreads();
    float inv = s_b;
    for (int s = tid; s < TT; s += 256) {
        if (s < len) p[s] *= inv;
        else         p[s] = 0.f;
    }
}

// ---------------- PV: o[t, h*40+d] = sum_s p[t,s] v[s, h*40+d] ----------------
__global__ void k_pv(const float* __restrict__ att, const float* __restrict__ v,
                     float* __restrict__ o) {
    int tt0 = blockIdx.x * 64;
    int bh = blockIdx.y;
    int b = bh / HH, h = bh - b * HH;
    const float* p  = att + ((size_t)bh * TT + tt0) * TT;
    const float* vb = v + (size_t)b * TT * DD + h * HDD;
    float* ob       = o + ((size_t)b * TT + tt0) * DD + h * HDD;
    int smax = tt0 + 64;                 // p is zero beyond the query tile's diagonal
    __shared__ float Ps[64][33];
    __shared__ float Vs[32][HDD];
    int tid = threadIdx.x;
    int tx = tid & 7, ty = tid >> 3;
    float acc[2][5] = {};
    for (int s0 = 0; s0 < smax; s0 += 32) {
        for (int i = tid; i < 64 * 32; i += 256) {
            int r = i >> 5, c = i & 31;
            Ps[r][c] = p[(size_t)r * TT + s0 + c];
        }
        for (int i = tid; i < 32 * HDD; i += 256) {
            int r = i / HDD, c = i - r * HDD;
            Vs[r][c] = vb[(size_t)(s0 + r) * DD + c];
        }
        __syncthreads();
        #pragma unroll
        for (int kk = 0; kk < 32; kk++) {
            float p0 = Ps[ty * 2 + 0][kk];
            float p1 = Ps[ty * 2 + 1][kk];
            #pragma unroll
            for (int j = 0; j < 5; j++) {
                float vv = Vs[kk][tx * 5 + j];
                acc[0][j] += p0 * vv;
                acc[1][j] += p1 * vv;
            }
        }
        __syncthreads();
    }
    #pragma unroll
    for (int i = 0; i < 2; i++)
        #pragma unroll
        for (int j = 0; j < 5; j++)
            ob[(size_t)(ty * 2 + i) * DD + tx * 5 + j] = acc[i][j];
}

// ---------------- launcher ----------------
extern "C" void kernel_launch(void* const* d_in, const int* in_sizes, int n_in,
                              void* d_out, int out_size) {
    const int*   idx = (const int*)  d_in[0];
    const float* emb = (const float*)d_in[1];
    const float* wq  = (const float*)d_in[2];
    const float* wk  = (const float*)d_in[3];
    const float* wv  = (const float*)d_in[4];
    const float* wo  = (const float*)d_in[5];
    const float* w1  = (const float*)d_in[6];
    const float* w2  = (const float*)d_in[7];
    const float* w3  = (const float*)d_in[8];
    const float* n1  = (const float*)d_in[9];
    const float* n2  = (const float*)d_in[10];
    const float* nw  = (const float*)d_in[11];
    float* out = (float*)d_out;

    float *x, *h, *q, *k, *v, *o, *gp, *att;
    cudaGetSymbolAddress((void**)&x,  g_x);
    cudaGetSymbolAddress((void**)&h,  g_h);
    cudaGetSymbolAddress((void**)&q,  g_q);
    cudaGetSymbolAddress((void**)&k,  g_k);
    cudaGetSymbolAddress((void**)&v,  g_v);
    cudaGetSymbolAddress((void**)&o,  g_o);
    cudaGetSymbolAddress((void**)&gp, g_gp);
    cudaGetSymbolAddress((void**)&att, g_att);

    k_embed<<<(MM * DD + 255) / 256, 256>>>(idx, emb, x);

    dim3 gD(5,  MM / 128);    // N = 280
    dim3 gF(18, MM / 128);    // N = 1120
    dim3 gV(4,  MM / 128);    // N = 256

    for (int l = 0; l < LL; l++) {
        size_t wOff = (size_t)l * DD * DD;
        k_rmsnorm<<<MM, 128>>>(x, n1 + l * DD, h);
        k_gemm_tc<false><<<gD, 256>>>(h, wq + wOff, q, DD, DD);
        k_gemm_tc<false><<<gD, 256>>>(h, wk + wOff, k, DD, DD);
        k_gemm_tc<false><<<gD, 256>>>(h, wv + wOff, v, DD, DD);
        k_rotary<<<(MM * HH * 20 + 255) / 256, 256>>>(q, k);
        k_score<<<dim3(8, 8, BB * HH), 256>>>(q, k, att);
        k_softmax<<<BB * HH * TT, 256>>>(att);
        k_pv<<<dim3(TT / 64, BB * HH), 256>>>(att, v, o);
        k_gemm_tc<true><<<gD, 256>>>(o, wo + wOff, x, DD, DD);
        k_rmsnorm<<<MM, 128>>>(x, n2 + l * DD, h);
        k_mlp_tc<<<gF, 256>>>(h, w1 + (size_t)l * FFD * DD, w3 + (size_t)l * FFD * DD, gp);
        k_gemm_tc<true><<<gD, 256>>>(gp, w2 + (size_t)l * DD * FFD, x, DD, FFD);
    }

    k_rmsnorm<<<MM, 128>>>(x, nw, h);
    k_gemm_tc<false><<<gV, 256>>>(h, emb, out, VV, DD);
}

// round 7
// speedup vs baseline: 2.1572x; 1.1864x over previous
#include <cuda_runtime.h>
#include <math.h>
#include <stdint.h>

#define DD 280
#define HH 7
#define HDD 40
#define LL 7
#define FFD 1120
#define VV 256
#define TT 512
#define BB 32
#define MM (BB*TT)   // 16384

// ---------------- scratch (device globals; no allocation allowed) ----------------
__device__ float g_x[MM*DD];
__device__ float g_h[MM*DD];
__device__ float g_q[MM*DD];
__device__ float g_k[MM*DD];
__device__ float g_v[MM*DD];
__device__ float g_o[MM*DD];
__device__ float g_gp[(size_t)MM*FFD];
__device__ float g_up[(size_t)MM*FFD];
__device__ float g_att[(size_t)BB*HH*TT*TT];

// ---------------- helpers ----------------
__device__ __forceinline__ float to_tf32(float x) {
    unsigned u;
    asm("cvt.rna.tf32.f32 %0, %1;" : "=r"(u) : "f"(x));
    return __uint_as_float(u);
}
__device__ __forceinline__ uint32_t smem_u32(const void* p) {
    uint32_t a;
    asm("{ .reg .u64 t; cvta.to.shared.u64 t, %1; cvt.u32.u64 %0, t; }" : "=r"(a) : "l"(p));
    return a;
}
__device__ __forceinline__ void mma8(float* d, const uint32_t* a, const uint32_t* b) {
    asm volatile(
        "mma.sync.aligned.m16n8k8.row.col.f32.tf32.tf32.f32 "
        "{%0,%1,%2,%3}, {%4,%5,%6,%7}, {%8,%9}, {%0,%1,%2,%3};\n"
        : "+f"(d[0]), "+f"(d[1]), "+f"(d[2]), "+f"(d[3])
        : "r"(a[0]), "r"(a[1]), "r"(a[2]), "r"(a[3]), "r"(b[0]), "r"(b[1]));
}
#define LDM4(r, addr) \
    asm volatile("ldmatrix.sync.aligned.m8n8.x4.shared.b16 {%0,%1,%2,%3}, [%4];" \
        : "=r"((r)[0]), "=r"((r)[1]), "=r"((r)[2]), "=r"((r)[3]) : "r"(addr))

// ============ tensor-core GEMM: C[M,N] = A[M,K] * W[N,K]^T (opt +=) ============
// 128x64 block tile, BK=32 double-buffered, 256 threads (8 warps, 4m x 2n),
// warp tile 32x32, ldmatrix fragment loads, stride-36 SMEM (conflict-free LDSM).
// blockIdx.z selects one of up to 3 (W, C) pairs sharing the same A.
#define AS_BUF 18432   // 128*36*4
#define WS_BUF 9216    // 64*36*4
#define SMEM_GEMM (2*AS_BUF + 2*WS_BUF)   // 55296

template<bool ADD>
__global__ void __launch_bounds__(256) k_gemm_tc(
        const float* __restrict__ A,
        const float* __restrict__ Wa, const float* __restrict__ Wb, const float* __restrict__ Wc,
        float* __restrict__ Ca, float* __restrict__ Cb, float* __restrict__ Cc,
        int N, int K) {
    const float* W = (blockIdx.z == 0) ? Wa : ((blockIdx.z == 1) ? Wb : Wc);
    float*       C = (blockIdx.z == 0) ? Ca : ((blockIdx.z == 1) ? Cb : Cc);
    extern __shared__ __align__(16) char smem[];
    uint32_t sA = smem_u32(smem);
    uint32_t sW = sA + 2 * AS_BUF;

    int m0 = blockIdx.y * 128, n0 = blockIdx.x * 64;
    int tid = threadIdx.x;
    int lane = tid & 31, warp = tid >> 5;
    int wm = (warp & 3) * 32, wn = (warp >> 2) * 32;
    int g = lane >> 2, q = lane & 3;

    // ldmatrix per-thread source rows/cols
    int arow = (lane & 7) + ((lane >> 3) & 1) * 8;
    int acol = (lane >> 4) * 4;
    int brow = (lane & 7) + (lane >> 4) * 8;
    int bcol = ((lane >> 3) & 1) * 4;
    uint32_t aAddr = sA + (uint32_t)((wm + arow) * 36 + acol) * 4;
    uint32_t bAddr = sW + (uint32_t)((wn + brow) * 36 + bcol) * 4;

    float4 pa[4], pw[2];
    const float4 Z4 = make_float4(0.f, 0.f, 0.f, 0.f);

    int NC = (K + 31) >> 5;

    auto ldg = [&](int c) {
        int kbase = c << 5;
        #pragma unroll
        for (int r = 0; r < 4; r++) {
            int i = tid + r * 256;            // 0..1023
            int row = i >> 3, f4 = i & 7;
            int k = kbase + f4 * 4;
            pa[r] = (k < K) ? *(const float4*)(A + (size_t)(m0 + row) * K + k) : Z4;
        }
        #pragma unroll
        for (int r = 0; r < 2; r++) {
            int i = tid + r * 256;            // 0..511
            int row = i >> 3, f4 = i & 7;
            int k = kbase + f4 * 4;
            bool ok = ((n0 + row) < N) && (k < K);
            pw[r] = ok ? *(const float4*)(W + (size_t)(n0 + row) * K + k) : Z4;
        }
    };
    auto sts = [&](int buf) {
        #pragma unroll
        for (int r = 0; r < 4; r++) {
            int i = tid + r * 256;
            int row = i >> 3, f4 = i & 7;
            float4 v = pa[r];
            v.x = to_tf32(v.x); v.y = to_tf32(v.y); v.z = to_tf32(v.z); v.w = to_tf32(v.w);
            *(float4*)(smem + buf * AS_BUF + (row * 36 + f4 * 4) * 4) = v;
        }
        #pragma unroll
        for (int r = 0; r < 2; r++) {
            int i = tid + r * 256;
            int row = i >> 3, f4 = i & 7;
            float4 v = pw[r];
            v.x = to_tf32(v.x); v.y = to_tf32(v.y); v.z = to_tf32(v.z); v.w = to_tf32(v.w);
            *(float4*)(smem + 2 * AS_BUF + buf * WS_BUF + (row * 36 + f4 * 4) * 4) = v;
        }
    };

    float acc[2][4][4] = {};

    ldg(0);
    sts(0);
    __syncthreads();

    for (int c = 0; c < NC; c++) {
        if (c + 1 < NC) ldg(c + 1);
        uint32_t aOff = aAddr + (uint32_t)(c & 1) * AS_BUF;
        uint32_t bOff = bAddr + (uint32_t)(c & 1) * WS_BUF;
        #pragma unroll
        for (int s = 0; s < 4; s++) {
            uint32_t ko = s * 32;             // 8 floats per k-slice
            uint32_t a0[4], a1[4], b0[4], b1[4];
            LDM4(a0, aOff + ko);
            LDM4(a1, aOff + ko + 16 * 144);   // +16 rows
            LDM4(b0, bOff + ko);
            LDM4(b1, bOff + ko + 16 * 144);
            mma8(acc[0][0], a0, b0);     mma8(acc[0][1], a0, b0 + 2);
            mma8(acc[0][2], a0, b1);     mma8(acc[0][3], a0, b1 + 2);
            mma8(acc[1][0], a1, b0);     mma8(acc[1][1], a1, b0 + 2);
            mma8(acc[1][2], a1, b1);     mma8(acc[1][3], a1, b1 + 2);
        }
        if (c + 1 < NC) sts((c + 1) & 1);
        __syncthreads();
    }

    #pragma unroll
    for (int mt = 0; mt < 2; mt++) {
        int r0 = m0 + wm + mt * 16 + g;
        #pragma unroll
        for (int nt = 0; nt < 4; nt++) {
            int c0 = n0 + wn + nt * 8 + 2 * q;
            if (c0 < N) {                     // N even, c0 even -> pair valid together
                float* d = acc[mt][nt];
                size_t o1 = (size_t)r0 * N + c0;
                size_t o2 = (size_t)(r0 + 8) * N + c0;
                if (ADD) {
                    C[o1] += d[0]; C[o1 + 1] += d[1];
                    C[o2] += d[2]; C[o2 + 1] += d[3];
                } else {
                    C[o1] = d[0]; C[o1 + 1] = d[1];
                    C[o2] = d[2]; C[o2 + 1] = d[3];
                }
            }
        }
    }
}

// ---------------- silu-mul: gp = silu(gp) * up ----------------
__global__ void k_silu(float* __restrict__ gp, const float* __restrict__ up) {
    size_t i = ((size_t)blockIdx.x * 256 + threadIdx.x) * 4;
    if (i >= (size_t)MM * FFD) return;
    float4 gv = *(float4*)(gp + i);
    float4 uv = *(const float4*)(up + i);
    gv.x = (gv.x / (1.f + __expf(-gv.x))) * uv.x;
    gv.y = (gv.y / (1.f + __expf(-gv.y))) * uv.y;
    gv.z = (gv.z / (1.f + __expf(-gv.z))) * uv.z;
    gv.w = (gv.w / (1.f + __expf(-gv.w))) * uv.w;
    *(float4*)(gp + i) = gv;
}

// ---------------- embed ----------------
__global__ void k_embed(const int* __restrict__ idx, const float* __restrict__ emb,
                        float* __restrict__ x) {
    int i = blockIdx.x * 256 + threadIdx.x;
    if (i >= MM * DD) return;
    int m = i / DD;
    int d = i - m * DD;
    x[i] = emb[idx[m] * DD + d];
}

// ---------------- rmsnorm: warp per row, 8 rows/block ----------------
__global__ void __launch_bounds__(256) k_rmsnorm(const float* __restrict__ x,
                                                 const float* __restrict__ w,
                                                 float* __restrict__ out) {
    int m = blockIdx.x * 8 + (threadIdx.x >> 5);
    int lane = threadIdx.x & 31;
    const float* xr = x + (size_t)m * DD;
    float v[9];
    float ss = 0.f;
    #pragma unroll
    for (int j = 0; j < 9; j++) {
        int d = lane + 32 * j;
        v[j] = (d < DD) ? xr[d] : 0.f;
        ss += v[j] * v[j];
    }
    #pragma unroll
    for (int o = 16; o; o >>= 1) ss += __shfl_xor_sync(0xffffffffu, ss, o);
    float sc = rsqrtf(ss / (float)DD + 1e-6f);
    float* orow = out + (size_t)m * DD;
    #pragma unroll
    for (int j = 0; j < 9; j++) {
        int d = lane + 32 * j;
        if (d < DD) orow[d] = v[j] * sc * w[d];
    }
}

// ---------------- rotary (q and k in-place) ----------------
__global__ void k_rotary(float* __restrict__ q, float* __restrict__ k) {
    int i = blockIdx.x * 256 + threadIdx.x;
    if (i >= MM * HH * (HDD / 2)) return;
    int p  = i % 20;
    int mh = i / 20;
    int h  = mh % HH;
    int m  = mh / HH;
    int t  = m & (TT - 1);
    float f = expf(-0.4605170186f * (float)p);   // 10000^{-p/20}
    float sv, cv;
    sincosf((float)t * f, &sv, &cv);
    size_t base = (size_t)m * DD + h * HDD + p;
    float a = q[base], b2 = q[base + 20];
    q[base]      = a  * cv - b2 * sv;
    q[base + 20] = b2 * cv + a  * sv;
    a = k[base]; b2 = k[base + 20];
    k[base]      = a  * cv - b2 * sv;
    k[base + 20] = b2 * cv + a  * sv;
}

// ---------------- attention scores (fp32 SIMT, exact) ----------------
__global__ void k_score(const float* __restrict__ q, const float* __restrict__ k,
                        float* __restrict__ att) {
    if (blockIdx.x > blockIdx.y) return;          // tile fully above diagonal
    int st0 = blockIdx.x * 64, tt0 = blockIdx.y * 64;
    int bh = blockIdx.z;
    int b = bh / HH, h = bh - b * HH;
    const float* qb = q + (size_t)b * TT * DD + h * HDD;
    const float* kb = k + (size_t)b * TT * DD + h * HDD;
    __shared__ float Qs[64][HDD];
    __shared__ float Ks[64][HDD];
    int tid = threadIdx.x;
    for (int i = tid; i < 64 * HDD; i += 256) {
        int r = i / HDD, c = i - r * HDD;
        Qs[r][c] = qb[(size_t)(tt0 + r) * DD + c];
        Ks[r][c] = kb[(size_t)(st0 + r) * DD + c];
    }
    __syncthreads();
    int tx = tid & 15, ty = tid >> 4;
    float acc[4][4] = {};
    #pragma unroll
    for (int kc = 0; kc < HDD; kc += 4) {
        float4 a[4], bb[4];
        #pragma unroll
        for (int i = 0; i < 4; i++) a[i]  = *reinterpret_cast<const float4*>(&Qs[ty * 4 + i][kc]);
        #pragma unroll
        for (int j = 0; j < 4; j++) bb[j] = *reinterpret_cast<const float4*>(&Ks[tx * 4 + j][kc]);
        #pragma unroll
        for (int i = 0; i < 4; i++)
            #pragma unroll
            for (int j = 0; j < 4; j++)
                acc[i][j] += a[i].x * bb[j].x + a[i].y * bb[j].y +
                             a[i].z * bb[j].z + a[i].w * bb[j].w;
    }
    const float scale = 0.1581138830f;  // 40^-0.5
    float* arow = att + ((size_t)bh * TT + tt0) * TT + st0;
    #pragma unroll
    for (int i = 0; i < 4; i++) {
        int t = tt0 + ty * 4 + i;
        #pragma unroll
        for (int j = 0; j < 4; j++) {
            int s = st0 + tx * 4 + j;
            arow[(size_t)(ty * 4 + i) * TT + tx * 4 + j] =
                (s <= t) ? acc[i][j] * scale : -1e30f;
        }
    }
}

// ---------------- causal softmax: warp per row, register-resident ----------------
__global__ void __launch_bounds__(256) k_softmax(float* __restrict__ att) {
    int row = blockIdx.x * 8 + (threadIdx.x >> 5);   // bh*T + t
    int lane = threadIdx.x & 31;
    int t = row & (TT - 1);
    float* p = att + (size_t)row * TT;
    int len = t + 1;
    float v[16];
    float mx = -3.4e38f;
    #pragma unroll
    for (int j = 0; j < 16; j++) {
        int s = lane + 32 * j;
        v[j] = (s < len) ? p[s] : -3.4e38f;
        mx = fmaxf(mx, v[j]);
    }
    #pragma unroll
    for (int o = 16; o; o >>= 1) mx = fmaxf(mx, __shfl_xor_sync(0xffffffffu, mx, o));
    float sum = 0.f;
    #pragma unroll
    for (int j = 0; j < 16; j++) {
        int s = lane + 32 * j;
        float e = (s < len) ? __expf(v[j] - mx) : 0.f;
        v[j] = e;
        sum += e;
    }
    #pragma unroll
    for (int o = 16; o; o >>= 1) sum += __shfl_xor_sync(0xffffffffu, sum, o);
    float inv = 1.f / sum;
    #pragma unroll
    for (int j = 0; j < 16; j++) p[lane + 32 * j] = v[j] * inv;
}

// ---------------- PV: o[t, h*40+d] = sum_s p[t,s] v[s, h*40+d] ----------------
__global__ void k_pv(const float* __restrict__ att, const float* __restrict__ v,
                     float* __restrict__ o) {
    int tt0 = blockIdx.x * 64;
    int bh = blockIdx.y;
    int b = bh / HH, h = bh - b * HH;
    const float* p  = att + ((size_t)bh * TT + tt0) * TT;
    const float* vb = v + (size_t)b * TT * DD + h * HDD;
    float* ob       = o + ((size_t)b * TT + tt0) * DD + h * HDD;
    int smax = tt0 + 64;                 // p is zero beyond the query tile's diagonal
    __shared__ float Ps[64][33];
    __shared__ float Vs[32][HDD];
    int tid = threadIdx.x;
    int tx = tid & 7, ty = tid >> 3;
    float acc[2][5] = {};
    for (int s0 = 0; s0 < smax; s0 += 32) {
        for (int i = tid; i < 64 * 32; i += 256) {
            int r = i >> 5, c = i & 31;
            Ps[r][c] = p[(size_t)r * TT + s0 + c];
        }
        for (int i = tid; i < 32 * HDD; i += 256) {
            int r = i / HDD, c = i - r * HDD;
            Vs[r][c] = vb[(size_t)(s0 + r) * DD + c];
        }
        __syncthreads();
        #pragma unroll
        for (int kk = 0; kk < 32; kk++) {
            float p0 = Ps[ty * 2 + 0][kk];
            float p1 = Ps[ty * 2 + 1][kk];
            #pragma unroll
            for (int j = 0; j < 5; j++) {
                float vv = Vs[kk][tx * 5 + j];
                acc[0][j] += p0 * vv;
                acc[1][j] += p1 * vv;
            }
        }
        __syncthreads();
    }
    #pragma unroll
    for (int i = 0; i < 2; i++)
        #pragma unroll
        for (int j = 0; j < 5; j++)
            ob[(size_t)(ty * 2 + i) * DD + tx * 5 + j] = acc[i][j];
}

// ---------------- launcher ----------------
extern "C" void kernel_launch(void* const* d_in, const int* in_sizes, int n_in,
                              void* d_out, int out_size) {
    const int*   idx = (const int*)  d_in[0];
    const float* emb = (const float*)d_in[1];
    const float* wq  = (const float*)d_in[2];
    const float* wk  = (const float*)d_in[3];
    const float* wv  = (const float*)d_in[4];
    const float* wo  = (const float*)d_in[5];
    const float* w1  = (const float*)d_in[6];
    const float* w2  = (const float*)d_in[7];
    const float* w3  = (const float*)d_in[8];
    const float* n1  = (const float*)d_in[9];
    const float* n2  = (const float*)d_in[10];
    const float* nw  = (const float*)d_in[11];
    float* out = (float*)d_out;

    float *x, *h, *q, *k, *v, *o, *gp, *up, *att;
    cudaGetSymbolAddress((void**)&x,  g_x);
    cudaGetSymbolAddress((void**)&h,  g_h);
    cudaGetSymbolAddress((void**)&q,  g_q);
    cudaGetSymbolAddress((void**)&k,  g_k);
    cudaGetSymbolAddress((void**)&v,  g_v);
    cudaGetSymbolAddress((void**)&o,  g_o);
    cudaGetSymbolAddress((void**)&gp, g_gp);
    cudaGetSymbolAddress((void**)&up, g_up);
    cudaGetSymbolAddress((void**)&att, g_att);

    cudaFuncSetAttribute(k_gemm_tc<false>, cudaFuncAttributeMaxDynamicSharedMemorySize, SMEM_GEMM);
    cudaFuncSetAttribute(k_gemm_tc<true>,  cudaFuncAttributeMaxDynamicSharedMemorySize, SMEM_GEMM);

    k_embed<<<(MM * DD + 255) / 256, 256>>>(idx, emb, x);

    dim3 gQKV(5, MM / 128, 3);   // N = 280, 3 outputs
    dim3 gD  (5, MM / 128, 1);   // N = 280
    dim3 gF  (18, MM / 128, 2);  // N = 1120, 2 outputs (W1, W3)
    dim3 gV  (4, MM / 128, 1);   // N = 256

    for (int l = 0; l < LL; l++) {
        size_t wOff = (size_t)l * DD * DD;
        size_t fOff = (size_t)l * FFD * DD;
        k_rmsnorm<<<MM / 8, 256>>>(x, n1 + l * DD, h);
        k_gemm_tc<false><<<gQKV, 256, SMEM_GEMM>>>(h, wq + wOff, wk + wOff, wv + wOff,
                                                   q, k, v, DD, DD);
        k_rotary<<<(MM * HH * 20 + 255) / 256, 256>>>(q, k);
        k_score<<<dim3(8, 8, BB * HH), 256>>>(q, k, att);
        k_softmax<<<BB * HH * TT / 8, 256>>>(att);
        k_pv<<<dim3(TT / 64, BB * HH), 256>>>(att, v, o);
        k_gemm_tc<true><<<gD, 256, SMEM_GEMM>>>(o, wo + wOff, 0, 0, x, 0, 0, DD, DD);
        k_rmsnorm<<<MM / 8, 256>>>(x, n2 + l * DD, h);
        k_gemm_tc<false><<<gF, 256, SMEM_GEMM>>>(h, w1 + fOff, w3 + fOff, 0,
                                                 gp, up, 0, FFD, DD);
        k_silu<<<(MM * FFD / 4 + 255) / 256, 256>>>(gp, up);
        k_gemm_tc<true><<<gD, 256, SMEM_GEMM>>>(gp, w2 + fOff, 0, 0, x, 0, 0, DD, FFD);
    }

    k_rmsnorm<<<MM / 8, 256>>>(x, nw, h);
    k_gemm_tc<false><<<gV, 256, SMEM_GEMM>>>(h, emb, 0, 0, out, 0, 0, VV, DD);
}

// round 9
// speedup vs baseline: 2.9246x; 1.3557x over previous
#include <cuda_runtime.h>
#include <math.h>
#include <stdint.h>

#define DD 280
#define HH 7
#define HDD 40
#define LL 7
#define FFD 1120
#define VV 256
#define TT 512
#define BB 32
#define MM (BB*TT)   // 16384

// ---------------- scratch (device globals; no allocation allowed) ----------------
__device__ float g_x[MM*DD];
__device__ float g_h[MM*DD];
__device__ float g_q[MM*DD];
__device__ float g_k[MM*DD];
__device__ float g_v[MM*DD];
__device__ float g_o[MM*DD];
__device__ float g_gp[(size_t)MM*FFD];

// ---------------- helpers ----------------
__device__ __forceinline__ float to_tf32(float x) {
    unsigned u;
    asm("cvt.rna.tf32.f32 %0, %1;" : "=r"(u) : "f"(x));
    return __uint_as_float(u);
}
__device__ __forceinline__ uint32_t smem_u32(const void* p) {
    uint32_t a;
    asm("{ .reg .u64 t; cvta.to.shared.u64 t, %1; cvt.u32.u64 %0, t; }" : "=r"(a) : "l"(p));
    return a;
}
__device__ __forceinline__ void mma8(float* d, const uint32_t* a, const uint32_t* b) {
    asm volatile(
        "mma.sync.aligned.m16n8k8.row.col.f32.tf32.tf32.f32 "
        "{%0,%1,%2,%3}, {%4,%5,%6,%7}, {%8,%9}, {%0,%1,%2,%3};\n"
        : "+f"(d[0]), "+f"(d[1]), "+f"(d[2]), "+f"(d[3])
        : "r"(a[0]), "r"(a[1]), "r"(a[2]), "r"(a[3]), "r"(b[0]), "r"(b[1]));
}
#define LDM4(r, addr) \
    asm volatile("ldmatrix.sync.aligned.m8n8.x4.shared.b16 {%0,%1,%2,%3}, [%4];" \
        : "=r"((r)[0]), "=r"((r)[1]), "=r"((r)[2]), "=r"((r)[3]) : "r"(addr))

// ============ tensor-core GEMM: C[M,N] = A[M,K] * W[N,K]^T (opt +=) ============
#define AS_BUF 18432   // 128*36*4
#define WS_BUF 9216    // 64*36*4
#define SMEM_GEMM (2*AS_BUF + 2*WS_BUF)   // 55296

template<bool ADD>
__global__ void __launch_bounds__(256) k_gemm_tc(
        const float* __restrict__ A,
        const float* __restrict__ Wa, const float* __restrict__ Wb, const float* __restrict__ Wc,
        float* __restrict__ Ca, float* __restrict__ Cb, float* __restrict__ Cc,
        int N, int K) {
    const float* W = (blockIdx.z == 0) ? Wa : ((blockIdx.z == 1) ? Wb : Wc);
    float*       C = (blockIdx.z == 0) ? Ca : ((blockIdx.z == 1) ? Cb : Cc);
    extern __shared__ __align__(16) char smem[];
    uint32_t sA = smem_u32(smem);
    uint32_t sW = sA + 2 * AS_BUF;

    int m0 = blockIdx.y * 128, n0 = blockIdx.x * 64;
    int tid = threadIdx.x;
    int lane = tid & 31, warp = tid >> 5;
    int wm = (warp & 3) * 32, wn = (warp >> 2) * 32;
    int g = lane >> 2, q = lane & 3;

    int arow = (lane & 7) + ((lane >> 3) & 1) * 8;
    int acol = (lane >> 4) * 4;
    int brow = (lane & 7) + (lane >> 4) * 8;
    int bcol = ((lane >> 3) & 1) * 4;
    uint32_t aAddr = sA + (uint32_t)((wm + arow) * 36 + acol) * 4;
    uint32_t bAddr = sW + (uint32_t)((wn + brow) * 36 + bcol) * 4;

    float4 pa[4], pw[2];
    const float4 Z4 = make_float4(0.f, 0.f, 0.f, 0.f);

    int NC = (K + 31) >> 5;

    auto ldg = [&](int c) {
        int kbase = c << 5;
        #pragma unroll
        for (int r = 0; r < 4; r++) {
            int i = tid + r * 256;
            int row = i >> 3, f4 = i & 7;
            int k = kbase + f4 * 4;
            pa[r] = (k < K) ? *(const float4*)(A + (size_t)(m0 + row) * K + k) : Z4;
        }
        #pragma unroll
        for (int r = 0; r < 2; r++) {
            int i = tid + r * 256;
            int row = i >> 3, f4 = i & 7;
            int k = kbase + f4 * 4;
            bool ok = ((n0 + row) < N) && (k < K);
            pw[r] = ok ? *(const float4*)(W + (size_t)(n0 + row) * K + k) : Z4;
        }
    };
    auto sts = [&](int buf) {
        #pragma unroll
        for (int r = 0; r < 4; r++) {
            int i = tid + r * 256;
            int row = i >> 3, f4 = i & 7;
            float4 v = pa[r];
            v.x = to_tf32(v.x); v.y = to_tf32(v.y); v.z = to_tf32(v.z); v.w = to_tf32(v.w);
            *(float4*)(smem + buf * AS_BUF + (row * 36 + f4 * 4) * 4) = v;
        }
        #pragma unroll
        for (int r = 0; r < 2; r++) {
            int i = tid + r * 256;
            int row = i >> 3, f4 = i & 7;
            float4 v = pw[r];
            v.x = to_tf32(v.x); v.y = to_tf32(v.y); v.z = to_tf32(v.z); v.w = to_tf32(v.w);
            *(float4*)(smem + 2 * AS_BUF + buf * WS_BUF + (row * 36 + f4 * 4) * 4) = v;
        }
    };

    float acc[2][4][4] = {};

    ldg(0);
    sts(0);
    __syncthreads();

    for (int c = 0; c < NC; c++) {
        if (c + 1 < NC) ldg(c + 1);
        uint32_t aOff = aAddr + (uint32_t)(c & 1) * AS_BUF;
        uint32_t bOff = bAddr + (uint32_t)(c & 1) * WS_BUF;
        #pragma unroll
        for (int s = 0; s < 4; s++) {
            uint32_t ko = s * 32;
            uint32_t a0[4], a1[4], b0[4], b1[4];
            LDM4(a0, aOff + ko);
            LDM4(a1, aOff + ko + 16 * 144);
            LDM4(b0, bOff + ko);
            LDM4(b1, bOff + ko + 16 * 144);
            mma8(acc[0][0], a0, b0);     mma8(acc[0][1], a0, b0 + 2);
            mma8(acc[0][2], a0, b1);     mma8(acc[0][3], a0, b1 + 2);
            mma8(acc[1][0], a1, b0);     mma8(acc[1][1], a1, b0 + 2);
            mma8(acc[1][2], a1, b1);     mma8(acc[1][3], a1, b1 + 2);
        }
        if (c + 1 < NC) sts((c + 1) & 1);
        __syncthreads();
    }

    #pragma unroll
    for (int mt = 0; mt < 2; mt++) {
        int r0 = m0 + wm + mt * 16 + g;
        #pragma unroll
        for (int nt = 0; nt < 4; nt++) {
            int c0 = n0 + wn + nt * 8 + 2 * q;
            if (c0 < N) {
                float* d = acc[mt][nt];
                size_t o1 = (size_t)r0 * N + c0;
                size_t o2 = (size_t)(r0 + 8) * N + c0;
                if (ADD) {
                    C[o1] += d[0]; C[o1 + 1] += d[1];
                    C[o2] += d[2]; C[o2 + 1] += d[3];
                } else {
                    C[o1] = d[0]; C[o1 + 1] = d[1];
                    C[o2] = d[2]; C[o2 + 1] = d[3];
                }
            }
        }
    }
}

// ============ fused MLP GEMM: Gp = silu(A*W1^T) * (A*W3^T) ============
#define SMEM_MLP (2*AS_BUF + 4*WS_BUF)   // 73728

__global__ void __launch_bounds__(256) k_mlp_tc(
        const float* __restrict__ A,
        const float* __restrict__ W1, const float* __restrict__ W3,
        float* __restrict__ Gp) {
    const int N = FFD, K = DD;
    extern __shared__ __align__(16) char smem[];
    uint32_t sA  = smem_u32(smem);
    uint32_t sW1 = sA + 2 * AS_BUF;
    uint32_t sW3 = sW1 + 2 * WS_BUF;

    int m0 = blockIdx.y * 128, n0 = blockIdx.x * 64;
    int tid = threadIdx.x;
    int lane = tid & 31, warp = tid >> 5;
    int wm = (warp & 3) * 32, wn = (warp >> 2) * 32;
    int g = lane >> 2, q = lane & 3;

    int arow = (lane & 7) + ((lane >> 3) & 1) * 8;
    int acol = (lane >> 4) * 4;
    int brow = (lane & 7) + (lane >> 4) * 8;
    int bcol = ((lane >> 3) & 1) * 4;
    uint32_t aAddr  = sA  + (uint32_t)((wm + arow) * 36 + acol) * 4;
    uint32_t b1Addr = sW1 + (uint32_t)((wn + brow) * 36 + bcol) * 4;
    uint32_t b3Addr = sW3 + (uint32_t)((wn + brow) * 36 + bcol) * 4;

    float4 pa[4], p1[2], p3[2];
    const float4 Z4 = make_float4(0.f, 0.f, 0.f, 0.f);
    int NC = (K + 31) >> 5;   // 9

    auto ldg = [&](int c) {
        int kbase = c << 5;
        #pragma unroll
        for (int r = 0; r < 4; r++) {
            int i = tid + r * 256;
            int row = i >> 3, f4 = i & 7;
            int k = kbase + f4 * 4;
            pa[r] = (k < K) ? *(const float4*)(A + (size_t)(m0 + row) * K + k) : Z4;
        }
        #pragma unroll
        for (int r = 0; r < 2; r++) {
            int i = tid + r * 256;
            int row = i >> 3, f4 = i & 7;
            int k = kbase + f4 * 4;
            bool ok = ((n0 + row) < N) && (k < K);     // FIX: row bound restored
            p1[r] = ok ? *(const float4*)(W1 + (size_t)(n0 + row) * K + k) : Z4;
            p3[r] = ok ? *(const float4*)(W3 + (size_t)(n0 + row) * K + k) : Z4;
        }
    };
    auto sts = [&](int buf) {
        #pragma unroll
        for (int r = 0; r < 4; r++) {
            int i = tid + r * 256;
            int row = i >> 3, f4 = i & 7;
            float4 v = pa[r];
            v.x = to_tf32(v.x); v.y = to_tf32(v.y); v.z = to_tf32(v.z); v.w = to_tf32(v.w);
            *(float4*)(smem + buf * AS_BUF + (row * 36 + f4 * 4) * 4) = v;
        }
        #pragma unroll
        for (int r = 0; r < 2; r++) {
            int i = tid + r * 256;
            int row = i >> 3, f4 = i & 7;
            float4 v = p1[r];
            v.x = to_tf32(v.x); v.y = to_tf32(v.y); v.z = to_tf32(v.z); v.w = to_tf32(v.w);
            *(float4*)(smem + 2 * AS_BUF + buf * WS_BUF + (row * 36 + f4 * 4) * 4) = v;
            v = p3[r];
            v.x = to_tf32(v.x); v.y = to_tf32(v.y); v.z = to_tf32(v.z); v.w = to_tf32(v.w);
            *(float4*)(smem + 2 * AS_BUF + 2 * WS_BUF + buf * WS_BUF + (row * 36 + f4 * 4) * 4) = v;
        }
    };

    float acc1[2][4][4] = {};
    float acc3[2][4][4] = {};

    ldg(0);
    sts(0);
    __syncthreads();

    for (int c = 0; c < NC; c++) {
        if (c + 1 < NC) ldg(c + 1);
        uint32_t aOff  = aAddr  + (uint32_t)(c & 1) * AS_BUF;
        uint32_t b1Off = b1Addr + (uint32_t)(c & 1) * WS_BUF;
        uint32_t b3Off = b3Addr + (uint32_t)(c & 1) * WS_BUF;
        #pragma unroll
        for (int s = 0; s < 4; s++) {
            uint32_t ko = s * 32;
            uint32_t a0[4], a1[4], b0[4], b1[4], c0[4], c1[4];
            LDM4(a0, aOff + ko);
            LDM4(a1, aOff + ko + 16 * 144);
            LDM4(b0, b1Off + ko);
            LDM4(b1, b1Off + ko + 16 * 144);
            LDM4(c0, b3Off + ko);
            LDM4(c1, b3Off + ko + 16 * 144);
            mma8(acc1[0][0], a0, b0);  mma8(acc1[0][1], a0, b0 + 2);
            mma8(acc1[0][2], a0, b1);  mma8(acc1[0][3], a0, b1 + 2);
            mma8(acc1[1][0], a1, b0);  mma8(acc1[1][1], a1, b0 + 2);
            mma8(acc1[1][2], a1, b1);  mma8(acc1[1][3], a1, b1 + 2);
            mma8(acc3[0][0], a0, c0);  mma8(acc3[0][1], a0, c0 + 2);
            mma8(acc3[0][2], a0, c1);  mma8(acc3[0][3], a0, c1 + 2);
            mma8(acc3[1][0], a1, c0);  mma8(acc3[1][1], a1, c0 + 2);
            mma8(acc3[1][2], a1, c1);  mma8(acc3[1][3], a1, c1 + 2);
        }
        if (c + 1 < NC) sts((c + 1) & 1);
        __syncthreads();
    }

    #pragma unroll
    for (int mt = 0; mt < 2; mt++) {
        int r0 = m0 + wm + mt * 16 + g;
        #pragma unroll
        for (int nt = 0; nt < 4; nt++) {
            int c0 = n0 + wn + nt * 8 + 2 * q;
            if (c0 < N) {                              // FIX: column bound restored
                float* dg = acc1[mt][nt];
                float* du = acc3[mt][nt];
                #pragma unroll
                for (int e = 0; e < 4; e++) {
                    float gg = dg[e], uu = du[e];
                    float sv = gg / (1.f + __expf(-gg));
                    int row = (e < 2) ? r0 : r0 + 8;
                    int col = c0 + (e & 1);
                    Gp[(size_t)row * N + col] = sv * uu;
                }
            }
        }
    }
}

// ---------------- embed ----------------
__global__ void k_embed(const int* __restrict__ idx, const float* __restrict__ emb,
                        float* __restrict__ x) {
    int i = blockIdx.x * 256 + threadIdx.x;
    if (i >= MM * DD) return;
    int m = i / DD;
    int d = i - m * DD;
    x[i] = emb[idx[m] * DD + d];
}

// ---------------- rmsnorm: warp per row, 8 rows/block ----------------
__global__ void __launch_bounds__(256) k_rmsnorm(const float* __restrict__ x,
                                                 const float* __restrict__ w,
                                                 float* __restrict__ out) {
    int m = blockIdx.x * 8 + (threadIdx.x >> 5);
    int lane = threadIdx.x & 31;
    const float* xr = x + (size_t)m * DD;
    float v[9];
    float ss = 0.f;
    #pragma unroll
    for (int j = 0; j < 9; j++) {
        int d = lane + 32 * j;
        v[j] = (d < DD) ? xr[d] : 0.f;
        ss += v[j] * v[j];
    }
    #pragma unroll
    for (int o = 16; o; o >>= 1) ss += __shfl_xor_sync(0xffffffffu, ss, o);
    float sc = rsqrtf(ss / (float)DD + 1e-6f);
    float* orow = out + (size_t)m * DD;
    #pragma unroll
    for (int j = 0; j < 9; j++) {
        int d = lane + 32 * j;
        if (d < DD) orow[d] = v[j] * sc * w[d];
    }
}

// ---------------- rotary (q and k in-place) ----------------
__global__ void k_rotary(float* __restrict__ q, float* __restrict__ k) {
    int i = blockIdx.x * 256 + threadIdx.x;
    if (i >= MM * HH * (HDD / 2)) return;
    int p  = i % 20;
    int mh = i / 20;
    int h  = mh % HH;
    int m  = mh / HH;
    int t  = m & (TT - 1);
    float f = expf(-0.4605170186f * (float)p);   // 10000^{-p/20}
    float sv, cv;
    sincosf((float)t * f, &sv, &cv);
    size_t base = (size_t)m * DD + h * HDD + p;
    float a = q[base], b2 = q[base + 20];
    q[base]      = a  * cv - b2 * sv;
    q[base + 20] = b2 * cv + a  * sv;
    a = k[base]; b2 = k[base + 20];
    k[base]      = a  * cv - b2 * sv;
    k[base + 20] = b2 * cv + a  * sv;
}

// ============ fused flash attention: o = softmax(qk^T, causal) v ============
// block = 256 threads, one (bh, 64-row q-tile) per block; K/V chunks of 32.
__global__ void __launch_bounds__(256) k_attn(const float* __restrict__ q,
                                              const float* __restrict__ k,
                                              const float* __restrict__ v,
                                              float* __restrict__ o) {
    int tt0 = blockIdx.x * 64;
    int bh = blockIdx.y;
    int b = bh / HH, h = bh - b * HH;
    const float* qb = q + (size_t)b * TT * DD + h * HDD;
    const float* kb = k + (size_t)b * TT * DD + h * HDD;
    const float* vb = v + (size_t)b * TT * DD + h * HDD;
    float* ob       = o + ((size_t)b * TT + tt0) * DD + h * HDD;

    __shared__ float Qs[64][41];
    __shared__ float Ks[32][41];
    __shared__ float Vs[32][41];
    __shared__ float Ps[64][33];
    __shared__ float s_m[64], s_l[64], s_al[64];

    int tid = threadIdx.x;
    int lane = tid & 31, warp = tid >> 5;
    int tx = tid & 7, ty = tid >> 3;
    const float scale = 0.1581138830f;   // 40^-0.5

    for (int i = tid; i < 64 * HDD; i += 256) {
        int r = i / HDD, c = i - r * HDD;
        Qs[r][c] = qb[(size_t)(tt0 + r) * DD + c] * scale;
    }
    if (tid < 64) { s_m[tid] = -3.0e38f; s_l[tid] = 0.f; }
    __syncthreads();

    float accO[2][5] = {};
    int send = tt0 + 64;

    for (int s0 = 0; s0 < send; s0 += 32) {
        for (int i = tid; i < 32 * HDD; i += 256) {
            int r = i / HDD, c = i - r * HDD;
            Ks[r][c] = kb[(size_t)(s0 + r) * DD + c];
            Vs[r][c] = vb[(size_t)(s0 + r) * DD + c];
        }
        __syncthreads();

        // --- scores: warp handles 8 q-rows, lane = s within chunk ---
        float kreg[HDD];
        #pragma unroll
        for (int d = 0; d < HDD; d++) kreg[d] = Ks[lane][d];
        int sglob = s0 + lane;
        int r0 = warp * 8;
        #pragma unroll
        for (int ri = 0; ri < 8; ri++) {
            int rglob = tt0 + r0 + ri;
            float acc = 0.f;
            #pragma unroll
            for (int d = 0; d < HDD; d++) acc += Qs[r0 + ri][d] * kreg[d];
            float sv = (sglob <= rglob) ? acc : -1.0e30f;
            float mx = sv;
            #pragma unroll
            for (int off = 16; off; off >>= 1)
                mx = fmaxf(mx, __shfl_xor_sync(0xffffffffu, mx, off));
            float mold = s_m[r0 + ri];
            float mnew = fmaxf(mold, mx);
            float p = __expf(sv - mnew);
            float ps = p;
            #pragma unroll
            for (int off = 16; off; off >>= 1)
                ps += __shfl_xor_sync(0xffffffffu, ps, off);
            Ps[r0 + ri][lane] = p;
            if (lane == 0) {
                float al = __expf(mold - mnew);
                s_al[r0 + ri] = al;
                s_m[r0 + ri]  = mnew;
                s_l[r0 + ri]  = al * s_l[r0 + ri] + ps;
            }
        }
        __syncthreads();

        // --- O update: thread = (2 rows ty, 5 d-cols tx) ---
        float a0 = s_al[ty * 2], a1 = s_al[ty * 2 + 1];
        #pragma unroll
        for (int j = 0; j < 5; j++) { accO[0][j] *= a0; accO[1][j] *= a1; }
        #pragma unroll
        for (int kk = 0; kk < 32; kk++) {
            float p0 = Ps[ty * 2][kk];
            float p1 = Ps[ty * 2 + 1][kk];
            #pragma unroll
            for (int j = 0; j < 5; j++) {
                float vv = Vs[kk][tx * 5 + j];
                accO[0][j] += p0 * vv;
                accO[1][j] += p1 * vv;
            }
        }
        __syncthreads();
    }

    float inv0 = 1.f / s_l[ty * 2];
    float inv1 = 1.f / s_l[ty * 2 + 1];
    #pragma unroll
    for (int j = 0; j < 5; j++) {
        ob[(size_t)(ty * 2 + 0) * DD + tx * 5 + j] = accO[0][j] * inv0;
        ob[(size_t)(ty * 2 + 1) * DD + tx * 5 + j] = accO[1][j] * inv1;
    }
}

// ---------------- launcher ----------------
extern "C" void kernel_launch(void* const* d_in, const int* in_sizes, int n_in,
                              void* d_out, int out_size) {
    const int*   idx = (const int*)  d_in[0];
    const float* emb = (const float*)d_in[1];
    const float* wq  = (const float*)d_in[2];
    const float* wk  = (const float*)d_in[3];
    const float* wv  = (const float*)d_in[4];
    const float* wo  = (const float*)d_in[5];
    const float* w1  = (const float*)d_in[6];
    const float* w2  = (const float*)d_in[7];
    const float* w3  = (const float*)d_in[8];
    const float* n1  = (const float*)d_in[9];
    const float* n2  = (const float*)d_in[10];
    const float* nw  = (const float*)d_in[11];
    float* out = (float*)d_out;

    float *x, *h, *q, *k, *v, *o, *gp;
    cudaGetSymbolAddress((void**)&x,  g_x);
    cudaGetSymbolAddress((void**)&h,  g_h);
    cudaGetSymbolAddress((void**)&q,  g_q);
    cudaGetSymbolAddress((void**)&k,  g_k);
    cudaGetSymbolAddress((void**)&v,  g_v);
    cudaGetSymbolAddress((void**)&o,  g_o);
    cudaGetSymbolAddress((void**)&gp, g_gp);

    cudaFuncSetAttribute(k_gemm_tc<false>, cudaFuncAttributeMaxDynamicSharedMemorySize, SMEM_GEMM);
    cudaFuncSetAttribute(k_gemm_tc<true>,  cudaFuncAttributeMaxDynamicSharedMemorySize, SMEM_GEMM);
    cudaFuncSetAttribute(k_mlp_tc,         cudaFuncAttributeMaxDynamicSharedMemorySize, SMEM_MLP);

    k_embed<<<(MM * DD + 255) / 256, 256>>>(idx, emb, x);

    dim3 gQKV(5, MM / 128, 3);   // N = 280, 3 outputs
    dim3 gD  (5, MM / 128, 1);   // N = 280
    dim3 gF  (18, MM / 128);     // N = 1120 fused MLP
    dim3 gV  (4, MM / 128, 1);   // N = 256

    for (int l = 0; l < LL; l++) {
        size_t wOff = (size_t)l * DD * DD;
        size_t fOff = (size_t)l * FFD * DD;
        k_rmsnorm<<<MM / 8, 256>>>(x, n1 + l * DD, h);
        k_gemm_tc<false><<<gQKV, 256, SMEM_GEMM>>>(h, wq + wOff, wk + wOff, wv + wOff,
                                                   q, k, v, DD, DD);
        k_rotary<<<(MM * HH * 20 + 255) / 256, 256>>>(q, k);
        k_attn<<<dim3(TT / 64, BB * HH), 256>>>(q, k, v, o);
        k_gemm_tc<true><<<gD, 256, SMEM_GEMM>>>(o, wo + wOff, 0, 0, x, 0, 0, DD, DD);
        k_rmsnorm<<<MM / 8, 256>>>(x, n2 + l * DD, h);
        k_mlp_tc<<<gF, 256, SMEM_MLP>>>(h, w1 + fOff, w3 + fOff, gp);
        k_gemm_tc<true><<<gD, 256, SMEM_GEMM>>>(gp, w2 + fOff, 0, 0, x, 0, 0, DD, FFD);
    }

    k_rmsnorm<<<MM / 8, 256>>>(x, nw, h);
    k_gemm_tc<false><<<gV, 256, SMEM_GEMM>>>(h, emb, 0, 0, out, 0, 0, VV, DD);
}